// round 3
// baseline (speedup 1.0000x reference)
#include <cuda_runtime.h>

#define FDIM 128
#define KH 5
#define NMAX 100000
#define EMAX 1600000
#define NBMAX 128
#define BN_EPS 1e-5f

typedef unsigned long long u64;

// ---------------- device scratch (static, no allocs) ----------------
__device__ float g_h[(size_t)NMAX * FDIM];     // h = x + agg   (51.2 MB)
__device__ float g_y[(size_t)NMAX * FDIM];     // y1            (51.2 MB)
__device__ u64   g_epack[EMAX];                // (w<<32)|col per CSR slot (12.8 MB)
__device__ int   g_cnt[NMAX];                  // per-node degree
__device__ int   g_rs[NMAX];                   // row start (CSR)
__device__ int   g_cur[NMAX];                  // fill cursor -> row end
__device__ int   g_bsum[NBMAX], g_boff[NBMAX];
__device__ u64   g_w1d[FDIM * FDIM];           // W duplicated into f32x2 lanes
__device__ u64   g_w2d[FDIM * FDIM];
__device__ float g_hopw[8];
__device__ float g_st1[256];                   // [0:128) colsum, [128:256) colsumsq
__device__ float g_st2[256];
__device__ float g_a1[FDIM], g_c1[FDIM];       // BN1 fused scale/shift
__device__ float g_a2[FDIM], g_c2[FDIM];       // BN2 fused scale/shift

// ---------------- f32x2 helpers ----------------
__device__ __forceinline__ u64 pk2(float lo, float hi) {
    u64 r;
    asm("mov.b64 %0, {%1, %2};" : "=l"(r) : "f"(lo), "f"(hi));
    return r;
}
__device__ __forceinline__ float2 upk2(u64 v) {
    float2 r;
    asm("mov.b64 {%0, %1}, %2;" : "=f"(r.x), "=f"(r.y) : "l"(v));
    return r;
}
#define FMA2(d, a, b) asm("fma.rn.f32x2 %0, %1, %2, %0;" : "+l"(d) : "l"(a), "l"(b))

__device__ __forceinline__ float4 ldcg4(const float4* p) {
    float4 v;
    asm("ld.global.cg.v4.f32 {%0,%1,%2,%3}, [%4];"
        : "=f"(v.x), "=f"(v.y), "=f"(v.z), "=f"(v.w) : "l"(p));
    return v;
}

// ---------------- softmax + zero stats ----------------
__global__ void k_prep(const float* __restrict__ hop_coef) {
    int t = threadIdx.x;
    if (t < 256) { g_st1[t] = 0.f; g_st2[t] = 0.f; }
    if (t == 0) {
        float v[KH];
        float m = -1e30f;
        for (int i = 0; i < KH; i++) { v[i] = hop_coef[i]; m = fmaxf(m, v[i]); }
        float s = 0.f;
        for (int i = 0; i < KH; i++) { v[i] = expf(v[i] - m); s += v[i]; }
        float inv = 1.f / s;
        for (int i = 0; i < KH; i++) g_hopw[i] = v[i] * inv;
    }
}

// ---------------- duplicate W into f32x2 lanes + zero cnt ----------------
__global__ void k_wdup(const float* __restrict__ W1, const float* __restrict__ W2) {
    int i = blockIdx.x * blockDim.x + threadIdx.x;
    if (i < FDIM * FDIM) {
        float a = W1[i], b = W2[i];
        g_w1d[i] = pk2(a, a);
        g_w2d[i] = pk2(b, b);
    }
}
__global__ void k_zero(int n) {
    int i = blockIdx.x * blockDim.x + threadIdx.x;
    if (i < n) g_cnt[i] = 0;
}

// ---------------- CSR build ----------------
__global__ void k_hist(const int* __restrict__ ei, const int* __restrict__ ew, int E) {
    int e = blockIdx.x * blockDim.x + threadIdx.x;
    if (e >= E) return;
    int d = ew[e];
    if (d < 1 || d > KH) return;
    atomicAdd(&g_cnt[ei[e]], 1);
}

__global__ void k_scan1(int n) {   // 1024 threads/block
    __shared__ int sh[1024];
    int i = blockIdx.x * 1024 + threadIdx.x;
    int v = (i < n) ? g_cnt[i] : 0;
    sh[threadIdx.x] = v;
    __syncthreads();
    for (int off = 1; off < 1024; off <<= 1) {
        int t = (threadIdx.x >= off) ? sh[threadIdx.x - off] : 0;
        __syncthreads();
        sh[threadIdx.x] += t;
        __syncthreads();
    }
    if (i < n) g_rs[i] = sh[threadIdx.x] - v;        // exclusive
    if (threadIdx.x == 1023) g_bsum[blockIdx.x] = sh[1023];
}
__global__ void k_scan2(int nb) {
    if (threadIdx.x == 0) {
        int acc = 0;
        for (int b = 0; b < nb; b++) { g_boff[b] = acc; acc += g_bsum[b]; }
    }
}
__global__ void k_scan3(int n) {
    int i = blockIdx.x * 1024 + threadIdx.x;
    if (i < n) {
        int s = g_rs[i] + g_boff[blockIdx.x];
        g_rs[i] = s;
        g_cur[i] = s;
    }
}

__global__ void k_edges(const int* __restrict__ ei, const int* __restrict__ ew, int E) {
    int e = blockIdx.x * blockDim.x + threadIdx.x;
    if (e >= E) return;
    int d = ew[e];
    if (d < 1 || d > KH) return;
    int r = ei[e];
    int c = ei[E + e];
    float w = g_hopw[d - 1];
    int pos = atomicAdd(&g_cur[r], 1);
    g_epack[pos] = ((u64)__float_as_uint(w) << 32) | (unsigned)c;
}

// ---------------- aggregate: one warp per node, h = x + sum(w * x[col]) ----------------
__global__ void k_aggr(const float4* __restrict__ x4, int n) {
    int node = (blockIdx.x * blockDim.x + threadIdx.x) >> 5;
    int lane = threadIdx.x & 31;
    if (node >= n) return;
    int s = g_rs[node], e = g_cur[node];
    float4 acc = __ldg(&x4[(size_t)node * 32 + lane]);
    for (int base = s; base < e; base += 32) {
        int m = min(32, e - base);
        u64 p = 0;
        if (lane < m) p = g_epack[base + lane];
        for (int j = 0; j < m; j++) {
            u64 pj = __shfl_sync(0xffffffffu, p, j);
            int c = (int)(unsigned)pj;
            float w = __uint_as_float((unsigned)(pj >> 32));
            float4 v = __ldg(&x4[(size_t)c * 32 + lane]);
            acc.x = fmaf(w, v.x, acc.x);
            acc.y = fmaf(w, v.y, acc.y);
            acc.z = fmaf(w, v.z, acc.z);
            acc.w = fmaf(w, v.w, acc.w);
        }
    }
    ((float4*)g_h)[(size_t)node * 32 + lane] = acc;
}

// ---------------- GEMM + fused BN-stats epilogue ----------------
// W read via L1 (pre-duplicated f32x2), A tile (64 rows) in smem via .cg loads.
// 256 threads: thread (tr=tid>>5, tc=tid&31) -> rows tr*8..+7, cols tc*4..+3.
template <int PHASE>
__global__ void __launch_bounds__(256, 4) k_gemm(float* __restrict__ OutY, int n) {
    const float* A = (PHASE == 1) ? g_h : g_y;
    float* Y       = (PHASE == 1) ? g_y : OutY;
    const ulonglong2* Wd = (const ulonglong2*)((PHASE == 1) ? g_w1d : g_w2d);

    __shared__ float As[64 * FDIM];
    __shared__ float sh_st[256];

    int tid = threadIdx.x;
    int tc = tid & 31, tr = tid >> 5;
    sh_st[tid] = 0.f;

    int row0 = blockIdx.x * 64;
    float4* As4 = (float4*)As;
    const float4* A4 = (const float4*)A;
    #pragma unroll
    for (int i = tid; i < 64 * 32; i += 256) {
        int r = i >> 5, c4 = i & 31;
        float4 v;
        if (row0 + r < n) {
            v = ldcg4(&A4[(size_t)(row0 + r) * 32 + c4]);
            if (PHASE == 2) {
                float4 a = __ldg(&((const float4*)g_a1)[c4]);
                float4 b = __ldg(&((const float4*)g_c1)[c4]);
                v.x = fmaxf(fmaf(a.x, v.x, b.x), 0.f);
                v.y = fmaxf(fmaf(a.y, v.y, b.y), 0.f);
                v.z = fmaxf(fmaf(a.z, v.z, b.z), 0.f);
                v.w = fmaxf(fmaf(a.w, v.w, b.w), 0.f);
            }
        } else {
            v = make_float4(0.f, 0.f, 0.f, 0.f);
        }
        As4[i] = v;
    }
    __syncthreads();

    u64 acc[4][4];
    #pragma unroll
    for (int p = 0; p < 4; p++)
        #pragma unroll
        for (int c = 0; c < 4; c++) acc[p][c] = 0ULL;

    int r0 = tr * 8;
    #pragma unroll 4
    for (int k = 0; k < FDIM; k++) {
        ulonglong2 wA = __ldg(&Wd[k * 64 + tc * 2]);      // dup W[k][4tc], W[k][4tc+1]
        ulonglong2 wB = __ldg(&Wd[k * 64 + tc * 2 + 1]);  // dup W[k][4tc+2], W[k][4tc+3]
        #pragma unroll
        for (int p = 0; p < 4; p++) {
            u64 ap = pk2(As[(r0 + 2 * p) * FDIM + k], As[(r0 + 2 * p + 1) * FDIM + k]);
            FMA2(acc[p][0], ap, wA.x);
            FMA2(acc[p][1], ap, wA.y);
            FMA2(acc[p][2], ap, wB.x);
            FMA2(acc[p][3], ap, wB.y);
        }
    }

    // epilogue: store Y + per-column stats
    float cs[4] = {0.f, 0.f, 0.f, 0.f};
    float cq[4] = {0.f, 0.f, 0.f, 0.f};
    #pragma unroll
    for (int p = 0; p < 4; p++) {
        float2 c0 = upk2(acc[p][0]);
        float2 c1 = upk2(acc[p][1]);
        float2 c2 = upk2(acc[p][2]);
        float2 c3 = upk2(acc[p][3]);
        int r_lo = row0 + r0 + 2 * p;
        int r_hi = r_lo + 1;
        if (r_lo < n) {
            float4 o = make_float4(c0.x, c1.x, c2.x, c3.x);
            ((float4*)Y)[(size_t)r_lo * 32 + tc] = o;
            cs[0] += o.x; cs[1] += o.y; cs[2] += o.z; cs[3] += o.w;
            cq[0] += o.x * o.x; cq[1] += o.y * o.y;
            cq[2] += o.z * o.z; cq[3] += o.w * o.w;
        }
        if (r_hi < n) {
            float4 o = make_float4(c0.y, c1.y, c2.y, c3.y);
            ((float4*)Y)[(size_t)r_hi * 32 + tc] = o;
            cs[0] += o.x; cs[1] += o.y; cs[2] += o.z; cs[3] += o.w;
            cq[0] += o.x * o.x; cq[1] += o.y * o.y;
            cq[2] += o.z * o.z; cq[3] += o.w * o.w;
        }
    }
    #pragma unroll
    for (int c = 0; c < 4; c++) {
        atomicAdd(&sh_st[tc * 4 + c], cs[c]);
        atomicAdd(&sh_st[128 + tc * 4 + c], cq[c]);
    }
    __syncthreads();
    float* gst = (PHASE == 1) ? g_st1 : g_st2;
    atomicAdd(&gst[tid], sh_st[tid]);
}

// ---------------- BN finalize ----------------
template <int PHASE>
__global__ void k_bnfin(const float* __restrict__ gamma,
                        const float* __restrict__ beta, float invN) {
    int i = threadIdx.x;
    const float* st = (PHASE == 1) ? g_st1 : g_st2;
    float mean = st[i] * invN;
    float var = st[i + 128] * invN - mean * mean;
    float s = gamma[i] * rsqrtf(var + BN_EPS);
    if (PHASE == 1) { g_a1[i] = s; g_c1[i] = beta[i] - mean * s; }
    else            { g_a2[i] = s; g_c2[i] = beta[i] - mean * s; }
}

// ---------------- final BN2 + ReLU in place on d_out ----------------
__global__ void k_final(float4* __restrict__ y, int n4) {
    for (int i = blockIdx.x * blockDim.x + threadIdx.x; i < n4;
         i += gridDim.x * blockDim.x) {
        int c4 = i & 31;
        float4 a = __ldg(&((const float4*)g_a2)[c4]);
        float4 b = __ldg(&((const float4*)g_c2)[c4]);
        float4 v = y[i];
        v.x = fmaxf(fmaf(a.x, v.x, b.x), 0.f);
        v.y = fmaxf(fmaf(a.y, v.y, b.y), 0.f);
        v.z = fmaxf(fmaf(a.z, v.z, b.z), 0.f);
        v.w = fmaxf(fmaf(a.w, v.w, b.w), 0.f);
        y[i] = v;
    }
}

// ---------------- launcher ----------------
extern "C" void kernel_launch(void* const* d_in, const int* in_sizes, int n_in,
                              void* d_out, int out_size) {
    const float* x    = (const float*)d_in[0];   // [N,128]
    const int*   ei   = (const int*)  d_in[1];   // [2,E]
    const int*   ew   = (const int*)  d_in[2];   // [E]
    const float* hop  = (const float*)d_in[3];   // [5]
    const float* W1   = (const float*)d_in[4];   // [128,128]
    const float* g1   = (const float*)d_in[6];
    const float* be1  = (const float*)d_in[7];
    const float* W2   = (const float*)d_in[8];
    const float* g2   = (const float*)d_in[10];
    const float* be2  = (const float*)d_in[11];
    float* out = (float*)d_out;

    int n = in_sizes[0] / FDIM;   // 100000
    int E = in_sizes[2];          // 1600000
    int n4 = n * 32;
    float invN = 1.f / (float)n;
    int nb = (n + 1023) / 1024;   // scan blocks

    k_prep<<<1, 256>>>(hop);
    k_wdup<<<(FDIM * FDIM + 255) / 256, 256>>>(W1, W2);
    k_zero<<<(n + 255) / 256, 256>>>(n);
    k_hist<<<(E + 255) / 256, 256>>>(ei, ew, E);
    k_scan1<<<nb, 1024>>>(n);
    k_scan2<<<1, 32>>>(nb);
    k_scan3<<<nb, 1024>>>(n);
    k_edges<<<(E + 255) / 256, 256>>>(ei, ew, E);
    k_aggr<<<(n * 32 + 255) / 256, 256>>>((const float4*)x, n);

    int gblocks = (n + 63) / 64;
    k_gemm<1><<<gblocks, 256>>>(nullptr, n);
    k_bnfin<1><<<1, 128>>>(g1, be1, invN);
    k_gemm<2><<<gblocks, 256>>>(out, n);
    k_bnfin<2><<<1, 128>>>(g2, be2, invN);
    k_final<<<2048, 256>>>((float4*)out, n4);
}

// round 4
// speedup vs baseline: 1.5618x; 1.5618x over previous
#include <cuda_runtime.h>

#define FDIM 128
#define KH 5
#define NMAX 100000
#define BN_EPS 1e-5f

typedef unsigned long long u64;

// ---------------- device scratch (static, no allocs) ----------------
__device__ float g_h[(size_t)NMAX * FDIM];   // agg (+x fused later)  (51.2 MB)
__device__ float g_y[(size_t)NMAX * FDIM];   // y1                    (51.2 MB)
__device__ float g_hopw[8];
__device__ float g_st1[256];                 // [0:128) colsum, [128:256) colsumsq
__device__ float g_st2[256];
__device__ float g_a1[FDIM], g_c1[FDIM];     // BN1 fused scale/shift
__device__ float g_a2[FDIM], g_c2[FDIM];     // BN2 fused scale/shift

// ---------------- f32x2 helpers ----------------
__device__ __forceinline__ u64 pk2(float lo, float hi) {
    u64 r;
    asm("mov.b64 %0, {%1, %2};" : "=l"(r) : "f"(lo), "f"(hi));
    return r;
}
__device__ __forceinline__ float2 upk2(u64 v) {
    float2 r;
    asm("mov.b64 {%0, %1}, %2;" : "=f"(r.x), "=f"(r.y) : "l"(v));
    return r;
}
#define FMA2(d, a, b) asm("fma.rn.f32x2 %0, %1, %2, %0;" : "+l"(d) : "l"(a), "l"(b))

__device__ __forceinline__ float4 ldcg4(const float4* p) {
    float4 v;
    asm("ld.global.cg.v4.f32 {%0,%1,%2,%3}, [%4];"
        : "=f"(v.x), "=f"(v.y), "=f"(v.z), "=f"(v.w) : "l"(p));
    return v;
}

// ---------------- softmax + zero stats ----------------
__global__ void k_prep(const float* __restrict__ hop_coef) {
    int t = threadIdx.x;
    if (t < 256) { g_st1[t] = 0.f; g_st2[t] = 0.f; }
    if (t == 0) {
        float v[KH];
        float m = -1e30f;
        for (int i = 0; i < KH; i++) { v[i] = hop_coef[i]; m = fmaxf(m, v[i]); }
        float s = 0.f;
        for (int i = 0; i < KH; i++) { v[i] = expf(v[i] - m); s += v[i]; }
        float inv = 1.f / s;
        for (int i = 0; i < KH; i++) g_hopw[i] = v[i] * inv;
    }
}

// ---------------- zero g_h (scatter accumulates into it each replay) ----------------
__global__ void k_zero_h(int n4) {
    float4 z = make_float4(0.f, 0.f, 0.f, 0.f);
    float4* h4 = (float4*)g_h;
    for (int i = blockIdx.x * blockDim.x + threadIdx.x; i < n4;
         i += gridDim.x * blockDim.x)
        h4[i] = z;
}

// ---------------- scatter-add messages: one warp per edge ----------------
__global__ void k_scatter(const float* __restrict__ x,
                          const int* __restrict__ ei,
                          const int* __restrict__ ew, int E) {
    int warp = (blockIdx.x * blockDim.x + threadIdx.x) >> 5;
    int lane = threadIdx.x & 31;
    if (warp >= E) return;
    int d = ew[warp];
    if (d < 1 || d > KH) return;
    float w = g_hopw[d - 1];
    int r = ei[warp];           // edge_index[0][e]
    int c = ei[E + warp];       // edge_index[1][e]
    float4 v = ldcg4(((const float4*)x) + (size_t)c * 32 + lane);
    v.x *= w; v.y *= w; v.z *= w; v.w *= w;
    atomicAdd(((float4*)g_h) + (size_t)r * 32 + lane, v);   // RED.128
}

// ---------------- GEMM + fused BN-stats epilogue ----------------
// PHASE 1: A = g_h + x (GIN self term fused), Y = g_y, stats -> g_st1
// PHASE 2: A = relu(a1*g_y + c1), Y = OutY, stats -> g_st2
// smem: A-tile only (32KB) -> 4 blocks/SM via 58% carveout; W via L1 __ldg.
// 256 threads: thread (tr=tid>>5, tc=tid&31) -> rows tr*8..+7, cols tc*4..+3.
template <int PHASE>
__global__ void __launch_bounds__(256) k_gemm(const float4* __restrict__ X,
                                              const float* __restrict__ W,
                                              float* __restrict__ OutY, int n) {
    const float* A = (PHASE == 1) ? g_h : g_y;
    float* Y       = (PHASE == 1) ? g_y : OutY;

    __shared__ float As[64 * FDIM];
    __shared__ float sh_st[256];

    int tid = threadIdx.x;
    int tc = tid & 31, tr = tid >> 5;
    sh_st[tid] = 0.f;

    int row0 = blockIdx.x * 64;
    float4* As4 = (float4*)As;
    const float4* A4 = (const float4*)A;
    #pragma unroll
    for (int i = tid; i < 64 * 32; i += 256) {
        int r = i >> 5, c4 = i & 31;
        float4 v;
        if (row0 + r < n) {
            v = ldcg4(&A4[(size_t)(row0 + r) * 32 + c4]);
            if (PHASE == 1) {
                float4 xv = ldcg4(&X[(size_t)(row0 + r) * 32 + c4]);
                v.x += xv.x; v.y += xv.y; v.z += xv.z; v.w += xv.w;
            } else {
                float4 a = __ldg(&((const float4*)g_a1)[c4]);
                float4 b = __ldg(&((const float4*)g_c1)[c4]);
                v.x = fmaxf(fmaf(a.x, v.x, b.x), 0.f);
                v.y = fmaxf(fmaf(a.y, v.y, b.y), 0.f);
                v.z = fmaxf(fmaf(a.z, v.z, b.z), 0.f);
                v.w = fmaxf(fmaf(a.w, v.w, b.w), 0.f);
            }
        } else {
            v = make_float4(0.f, 0.f, 0.f, 0.f);
        }
        As4[i] = v;
    }
    __syncthreads();

    u64 acc[4][4];
    #pragma unroll
    for (int p = 0; p < 4; p++)
        #pragma unroll
        for (int c = 0; c < 4; c++) acc[p][c] = 0ULL;

    const float4* W4 = (const float4*)W;
    int r0 = tr * 8;
    #pragma unroll 4
    for (int k = 0; k < FDIM; k++) {
        float4 wv = __ldg(&W4[k * 32 + tc]);   // W[k][4tc..4tc+3], L1-resident
        u64 w0 = pk2(wv.x, wv.x);
        u64 w1 = pk2(wv.y, wv.y);
        u64 w2 = pk2(wv.z, wv.z);
        u64 w3 = pk2(wv.w, wv.w);
        #pragma unroll
        for (int p = 0; p < 4; p++) {
            u64 ap = pk2(As[(r0 + 2 * p) * FDIM + k], As[(r0 + 2 * p + 1) * FDIM + k]);
            FMA2(acc[p][0], ap, w0);
            FMA2(acc[p][1], ap, w1);
            FMA2(acc[p][2], ap, w2);
            FMA2(acc[p][3], ap, w3);
        }
    }

    // epilogue: store Y + per-column stats
    float cs[4] = {0.f, 0.f, 0.f, 0.f};
    float cq[4] = {0.f, 0.f, 0.f, 0.f};
    #pragma unroll
    for (int p = 0; p < 4; p++) {
        float2 c0 = upk2(acc[p][0]);
        float2 c1 = upk2(acc[p][1]);
        float2 c2 = upk2(acc[p][2]);
        float2 c3 = upk2(acc[p][3]);
        int r_lo = row0 + r0 + 2 * p;
        int r_hi = r_lo + 1;
        if (r_lo < n) {
            float4 o = make_float4(c0.x, c1.x, c2.x, c3.x);
            ((float4*)Y)[(size_t)r_lo * 32 + tc] = o;
            cs[0] += o.x; cs[1] += o.y; cs[2] += o.z; cs[3] += o.w;
            cq[0] += o.x * o.x; cq[1] += o.y * o.y;
            cq[2] += o.z * o.z; cq[3] += o.w * o.w;
        }
        if (r_hi < n) {
            float4 o = make_float4(c0.y, c1.y, c2.y, c3.y);
            ((float4*)Y)[(size_t)r_hi * 32 + tc] = o;
            cs[0] += o.x; cs[1] += o.y; cs[2] += o.z; cs[3] += o.w;
            cq[0] += o.x * o.x; cq[1] += o.y * o.y;
            cq[2] += o.z * o.z; cq[3] += o.w * o.w;
        }
    }
    #pragma unroll
    for (int c = 0; c < 4; c++) {
        atomicAdd(&sh_st[tc * 4 + c], cs[c]);
        atomicAdd(&sh_st[128 + tc * 4 + c], cq[c]);
    }
    __syncthreads();
    float* gst = (PHASE == 1) ? g_st1 : g_st2;
    atomicAdd(&gst[tid], sh_st[tid]);
}

// ---------------- BN finalize ----------------
template <int PHASE>
__global__ void k_bnfin(const float* __restrict__ gamma,
                        const float* __restrict__ beta, float invN) {
    int i = threadIdx.x;
    const float* st = (PHASE == 1) ? g_st1 : g_st2;
    float mean = st[i] * invN;
    float var = st[i + 128] * invN - mean * mean;
    float s = gamma[i] * rsqrtf(var + BN_EPS);
    if (PHASE == 1) { g_a1[i] = s; g_c1[i] = beta[i] - mean * s; }
    else            { g_a2[i] = s; g_c2[i] = beta[i] - mean * s; }
}

// ---------------- final BN2 + ReLU in place on d_out ----------------
__global__ void k_final(float4* __restrict__ y, int n4) {
    for (int i = blockIdx.x * blockDim.x + threadIdx.x; i < n4;
         i += gridDim.x * blockDim.x) {
        int c4 = i & 31;
        float4 a = __ldg(&((const float4*)g_a2)[c4]);
        float4 b = __ldg(&((const float4*)g_c2)[c4]);
        float4 v = y[i];
        v.x = fmaxf(fmaf(a.x, v.x, b.x), 0.f);
        v.y = fmaxf(fmaf(a.y, v.y, b.y), 0.f);
        v.z = fmaxf(fmaf(a.z, v.z, b.z), 0.f);
        v.w = fmaxf(fmaf(a.w, v.w, b.w), 0.f);
        y[i] = v;
    }
}

// ---------------- launcher ----------------
extern "C" void kernel_launch(void* const* d_in, const int* in_sizes, int n_in,
                              void* d_out, int out_size) {
    const float* x    = (const float*)d_in[0];   // [N,128]
    const int*   ei   = (const int*)  d_in[1];   // [2,E]
    const int*   ew   = (const int*)  d_in[2];   // [E]
    const float* hop  = (const float*)d_in[3];   // [5]
    const float* W1   = (const float*)d_in[4];   // [128,128]
    const float* g1   = (const float*)d_in[6];
    const float* be1  = (const float*)d_in[7];
    const float* W2   = (const float*)d_in[8];
    const float* g2   = (const float*)d_in[10];
    const float* be2  = (const float*)d_in[11];
    float* out = (float*)d_out;

    int n = in_sizes[0] / FDIM;   // 100000
    int E = in_sizes[2];          // 1600000
    int n4 = n * 32;
    float invN = 1.f / (float)n;

    // 58% carveout -> ~132KB smem pool -> 4 blocks/SM (33KB each), L1 ~96KB >= W(64KB)
    static int carveout_set = 0;
    if (!carveout_set) {
        cudaFuncSetAttribute(k_gemm<1>, cudaFuncAttributePreferredSharedMemoryCarveout, 58);
        cudaFuncSetAttribute(k_gemm<2>, cudaFuncAttributePreferredSharedMemoryCarveout, 58);
        carveout_set = 1;
    }

    k_prep<<<1, 256>>>(hop);
    k_zero_h<<<2048, 256>>>(n4);
    k_scatter<<<(E + 7) / 8, 256>>>(x, ei, ew, E);

    int gblocks = (n + 63) / 64;
    k_gemm<1><<<gblocks, 256>>>((const float4*)x, W1, nullptr, n);
    k_bnfin<1><<<1, 128>>>(g1, be1, invN);
    k_gemm<2><<<gblocks, 256>>>(nullptr, W2, out, n);
    k_bnfin<2><<<1, 128>>>(g2, be2, invN);
    k_final<<<2048, 256>>>((float4*)out, n4);
}

// round 5
// speedup vs baseline: 1.7794x; 1.1394x over previous
#include <cuda_runtime.h>

#define FDIM 128
#define KH 5
#define NMAX 100000
#define BN_EPS 1e-5f

typedef unsigned long long u64;

// ---------------- device scratch (static, no allocs) ----------------
__device__ float g_h[(size_t)NMAX * FDIM];   // agg  (51.2 MB)
__device__ float g_y[(size_t)NMAX * FDIM];   // y1   (51.2 MB)
__device__ float g_hopw[8];
__device__ float g_st1[256];                 // [0:128) colsum, [128:256) colsumsq
__device__ float g_st2[256];
__device__ float g_a1[FDIM], g_c1[FDIM];     // BN1 fused scale/shift
__device__ float g_a2[FDIM], g_c2[FDIM];     // BN2 fused scale/shift

// ---------------- f32x2 helpers ----------------
__device__ __forceinline__ u64 pk2(float lo, float hi) {
    u64 r;
    asm("mov.b64 %0, {%1, %2};" : "=l"(r) : "f"(lo), "f"(hi));
    return r;
}
__device__ __forceinline__ float2 upk2(u64 v) {
    float2 r;
    asm("mov.b64 {%0, %1}, %2;" : "=f"(r.x), "=f"(r.y) : "l"(v));
    return r;
}
#define FMA2(d, a, b) asm("fma.rn.f32x2 %0, %1, %2, %0;" : "+l"(d) : "l"(a), "l"(b))

// ---------------- softmax + zero stats ----------------
__global__ void k_prep(const float* __restrict__ hop_coef) {
    int t = threadIdx.x;
    if (t < 256) { g_st1[t] = 0.f; g_st2[t] = 0.f; }
    if (t == 0) {
        float v[KH];
        float m = -1e30f;
        for (int i = 0; i < KH; i++) { v[i] = hop_coef[i]; m = fmaxf(m, v[i]); }
        float s = 0.f;
        for (int i = 0; i < KH; i++) { v[i] = expf(v[i] - m); s += v[i]; }
        float inv = 1.f / s;
        for (int i = 0; i < KH; i++) g_hopw[i] = v[i] * inv;
    }
}

// ---------------- zero g_h ----------------
__global__ void k_zero_h(int n4) {
    float4 z = make_float4(0.f, 0.f, 0.f, 0.f);
    float4* h4 = (float4*)g_h;
    for (int i = blockIdx.x * blockDim.x + threadIdx.x; i < n4;
         i += gridDim.x * blockDim.x)
        h4[i] = z;
}

// ---------------- scatter-add messages: one warp per edge (proven R2 form) ----------------
__global__ void k_scatter(const float* __restrict__ x,
                          const int* __restrict__ ei,
                          const int* __restrict__ ew, int E) {
    int warp = (blockIdx.x * blockDim.x + threadIdx.x) >> 5;
    int lane = threadIdx.x & 31;
    if (warp >= E) return;
    int d = ew[warp];
    if (d < 1 || d > KH) return;
    float w = g_hopw[d - 1];
    int r = ei[warp];           // edge_index[0][e]
    int c = ei[E + warp];       // edge_index[1][e]
    float4 v = ((const float4*)x)[(size_t)c * 32 + lane];
    v.x *= w; v.y *= w; v.z *= w; v.w *= w;
    atomicAdd(((float4*)g_h) + (size_t)r * 32 + lane, v);   // RED.128
}

// ---------------- GEMM + fused BN-stats epilogue ----------------
// PHASE 1: A = g_h + x (GIN self term fused at stage), Y = g_y, stats -> g_st1
// PHASE 2: A = relu(a1*g_y + c1), Y = OutY, stats -> g_st2
// A tile stored TRANSPOSED At[k][r] so row-pairs are broadcast LDS.64.
// 256 threads: (tr=tid>>5, tc=tid&31) -> rows tr*8..+7, cols tc*4..+3.
template <int PHASE>
__global__ void __launch_bounds__(256) k_gemm(const float4* __restrict__ X,
                                              const float* __restrict__ W,
                                              float* __restrict__ OutY, int n) {
    const float* A = (PHASE == 1) ? g_h : g_y;
    float* Y       = (PHASE == 1) ? g_y : OutY;

    __shared__ __align__(16) float Ws[FDIM * 128];   // [k][c]  64 KB
    __shared__ __align__(16) float At[FDIM * 64];    // [k][r]  32 KB (transposed)
    __shared__ float sh_st[256];

    int tid = threadIdx.x;
    int tc = tid & 31, tr = tid >> 5;
    sh_st[tid] = 0.f;

    // stage W (coalesced, row-major [k][c])
    const float4* W4 = (const float4*)W;
    float4* Ws4 = (float4*)Ws;
    #pragma unroll 4
    for (int i = tid; i < FDIM * 32; i += 256) Ws4[i] = W4[i];

    // stage A transposed: i -> (c4 = i>>6, r = i&63); within a warp lanes span r
    // => STS banks = r%32 conflict-free; LDG 512B-strided but sector-complete.
    int row0 = blockIdx.x * 64;
    const float4* A4 = (const float4*)A;
    #pragma unroll
    for (int i = tid; i < 2048; i += 256) {
        int c4 = i >> 6, r = i & 63;
        float4 v = make_float4(0.f, 0.f, 0.f, 0.f);
        if (row0 + r < n) {
            v = A4[(size_t)(row0 + r) * 32 + c4];
            if (PHASE == 1) {
                float4 xv = X[(size_t)(row0 + r) * 32 + c4];
                v.x += xv.x; v.y += xv.y; v.z += xv.z; v.w += xv.w;
            } else {
                float4 a = __ldg(&((const float4*)g_a1)[c4]);
                float4 b = __ldg(&((const float4*)g_c1)[c4]);
                v.x = fmaxf(fmaf(a.x, v.x, b.x), 0.f);
                v.y = fmaxf(fmaf(a.y, v.y, b.y), 0.f);
                v.z = fmaxf(fmaf(a.z, v.z, b.z), 0.f);
                v.w = fmaxf(fmaf(a.w, v.w, b.w), 0.f);
            }
        }
        int k0 = c4 * 4;
        At[(k0 + 0) * 64 + r] = v.x;
        At[(k0 + 1) * 64 + r] = v.y;
        At[(k0 + 2) * 64 + r] = v.z;
        At[(k0 + 3) * 64 + r] = v.w;
    }
    __syncthreads();

    u64 acc[4][4];
    #pragma unroll
    for (int p = 0; p < 4; p++)
        #pragma unroll
        for (int c = 0; c < 4; c++) acc[p][c] = 0ULL;

    int r0 = tr * 8;
    #pragma unroll 4
    for (int k = 0; k < FDIM; k++) {
        float4 wv = Ws4[k * 32 + tc];                    // LDS.128, conflict-free
        u64 w0 = pk2(wv.x, wv.x);
        u64 w1 = pk2(wv.y, wv.y);
        u64 w2 = pk2(wv.z, wv.z);
        u64 w3 = pk2(wv.w, wv.w);
        const u64* ak = (const u64*)&At[k * 64 + r0];    // broadcast LDS.64 pairs
        u64 a0 = ak[0];
        u64 a1 = ak[1];
        u64 a2 = ak[2];
        u64 a3 = ak[3];
        FMA2(acc[0][0], a0, w0); FMA2(acc[0][1], a0, w1);
        FMA2(acc[0][2], a0, w2); FMA2(acc[0][3], a0, w3);
        FMA2(acc[1][0], a1, w0); FMA2(acc[1][1], a1, w1);
        FMA2(acc[1][2], a1, w2); FMA2(acc[1][3], a1, w3);
        FMA2(acc[2][0], a2, w0); FMA2(acc[2][1], a2, w1);
        FMA2(acc[2][2], a2, w2); FMA2(acc[2][3], a2, w3);
        FMA2(acc[3][0], a3, w0); FMA2(acc[3][1], a3, w1);
        FMA2(acc[3][2], a3, w2); FMA2(acc[3][3], a3, w3);
    }

    // epilogue: store Y + per-column stats
    float cs[4] = {0.f, 0.f, 0.f, 0.f};
    float cq[4] = {0.f, 0.f, 0.f, 0.f};
    #pragma unroll
    for (int p = 0; p < 4; p++) {
        float2 c0 = upk2(acc[p][0]);
        float2 c1 = upk2(acc[p][1]);
        float2 c2 = upk2(acc[p][2]);
        float2 c3 = upk2(acc[p][3]);
        int r_lo = row0 + r0 + 2 * p;
        int r_hi = r_lo + 1;
        if (r_lo < n) {
            float4 o = make_float4(c0.x, c1.x, c2.x, c3.x);
            ((float4*)Y)[(size_t)r_lo * 32 + tc] = o;
            cs[0] += o.x; cs[1] += o.y; cs[2] += o.z; cs[3] += o.w;
            cq[0] += o.x * o.x; cq[1] += o.y * o.y;
            cq[2] += o.z * o.z; cq[3] += o.w * o.w;
        }
        if (r_hi < n) {
            float4 o = make_float4(c0.y, c1.y, c2.y, c3.y);
            ((float4*)Y)[(size_t)r_hi * 32 + tc] = o;
            cs[0] += o.x; cs[1] += o.y; cs[2] += o.z; cs[3] += o.w;
            cq[0] += o.x * o.x; cq[1] += o.y * o.y;
            cq[2] += o.z * o.z; cq[3] += o.w * o.w;
        }
    }
    #pragma unroll
    for (int c = 0; c < 4; c++) {
        atomicAdd(&sh_st[tc * 4 + c], cs[c]);
        atomicAdd(&sh_st[128 + tc * 4 + c], cq[c]);
    }
    __syncthreads();
    float* gst = (PHASE == 1) ? g_st1 : g_st2;
    atomicAdd(&gst[tid], sh_st[tid]);
}

// ---------------- BN finalize ----------------
template <int PHASE>
__global__ void k_bnfin(const float* __restrict__ gamma,
                        const float* __restrict__ beta, float invN) {
    int i = threadIdx.x;
    const float* st = (PHASE == 1) ? g_st1 : g_st2;
    float mean = st[i] * invN;
    float var = st[i + 128] * invN - mean * mean;
    float s = gamma[i] * rsqrtf(var + BN_EPS);
    if (PHASE == 1) { g_a1[i] = s; g_c1[i] = beta[i] - mean * s; }
    else            { g_a2[i] = s; g_c2[i] = beta[i] - mean * s; }
}

// ---------------- final BN2 + ReLU in place on d_out ----------------
__global__ void k_final(float4* __restrict__ y, int n4) {
    for (int i = blockIdx.x * blockDim.x + threadIdx.x; i < n4;
         i += gridDim.x * blockDim.x) {
        int c4 = i & 31;
        float4 a = __ldg(&((const float4*)g_a2)[c4]);
        float4 b = __ldg(&((const float4*)g_c2)[c4]);
        float4 v = y[i];
        v.x = fmaxf(fmaf(a.x, v.x, b.x), 0.f);
        v.y = fmaxf(fmaf(a.y, v.y, b.y), 0.f);
        v.z = fmaxf(fmaf(a.z, v.z, b.z), 0.f);
        v.w = fmaxf(fmaf(a.w, v.w, b.w), 0.f);
        y[i] = v;
    }
}

// ---------------- launcher ----------------
extern "C" void kernel_launch(void* const* d_in, const int* in_sizes, int n_in,
                              void* d_out, int out_size) {
    const float* x    = (const float*)d_in[0];   // [N,128]
    const int*   ei   = (const int*)  d_in[1];   // [2,E]
    const int*   ew   = (const int*)  d_in[2];   // [E]
    const float* hop  = (const float*)d_in[3];   // [5]
    const float* W1   = (const float*)d_in[4];   // [128,128]
    const float* g1   = (const float*)d_in[6];
    const float* be1  = (const float*)d_in[7];
    const float* W2   = (const float*)d_in[8];
    const float* g2   = (const float*)d_in[10];
    const float* be2  = (const float*)d_in[11];
    float* out = (float*)d_out;

    int n = in_sizes[0] / FDIM;   // 100000
    int E = in_sizes[2];          // 1600000
    int n4 = n * 32;
    float invN = 1.f / (float)n;

    k_prep<<<1, 256>>>(hop);
    k_zero_h<<<2048, 256>>>(n4);
    k_scatter<<<(E + 7) / 8, 256>>>(x, ei, ew, E);

    int gblocks = (n + 63) / 64;
    k_gemm<1><<<gblocks, 256>>>((const float4*)x, W1, nullptr, n);
    k_bnfin<1><<<1, 128>>>(g1, be1, invN);
    k_gemm<2><<<gblocks, 256>>>(nullptr, W2, out, n);
    k_bnfin<2><<<1, 128>>>(g2, be2, invN);
    k_final<<<2048, 256>>>((float4*)out, n4);
}

// round 6
// speedup vs baseline: 2.2939x; 1.2891x over previous
#include <cuda_runtime.h>

#define FDIM 128
#define KH 5
#define NMAX 100000
#define BN_EPS 1e-5f

typedef unsigned long long u64;

// ---------------- device scratch (static, no allocs) ----------------
__device__ float g_h[(size_t)NMAX * FDIM];   // agg  (51.2 MB)
__device__ float g_y[(size_t)NMAX * FDIM];   // y1   (51.2 MB)
__device__ float g_hopw[8];
__device__ float g_st1[256];                 // [0:128) colsum, [128:256) colsumsq
__device__ float g_st2[256];
__device__ float g_a1[FDIM], g_c1[FDIM];     // BN1 fused scale/shift
__device__ float g_a2[FDIM], g_c2[FDIM];     // BN2 fused scale/shift

// ---------------- f32x2 helpers ----------------
__device__ __forceinline__ u64 pk2(float lo, float hi) {
    u64 r;
    asm("mov.b64 %0, {%1, %2};" : "=l"(r) : "f"(lo), "f"(hi));
    return r;
}
__device__ __forceinline__ float2 upk2(u64 v) {
    float2 r;
    asm("mov.b64 {%0, %1}, %2;" : "=f"(r.x), "=f"(r.y) : "l"(v));
    return r;
}
#define FMA2(d, a, b) asm("fma.rn.f32x2 %0, %1, %2, %0;" : "+l"(d) : "l"(a), "l"(b))

// ---------------- softmax + zero stats ----------------
__global__ void k_prep(const float* __restrict__ hop_coef) {
    int t = threadIdx.x;
    if (t < 256) { g_st1[t] = 0.f; g_st2[t] = 0.f; }
    if (t == 0) {
        float v[KH];
        float m = -1e30f;
        for (int i = 0; i < KH; i++) { v[i] = hop_coef[i]; m = fmaxf(m, v[i]); }
        float s = 0.f;
        for (int i = 0; i < KH; i++) { v[i] = expf(v[i] - m); s += v[i]; }
        float inv = 1.f / s;
        for (int i = 0; i < KH; i++) g_hopw[i] = v[i] * inv;
    }
}

// ---------------- zero g_h ----------------
__global__ void k_zero_h(int n4) {
    float4 z = make_float4(0.f, 0.f, 0.f, 0.f);
    float4* h4 = (float4*)g_h;
    for (int i = blockIdx.x * blockDim.x + threadIdx.x; i < n4;
         i += gridDim.x * blockDim.x)
        h4[i] = z;
}

// ---------------- scatter-add: warp handles 32 edges, meta de-duplicated ----------------
__global__ void k_scatter(const float* __restrict__ x,
                          const int* __restrict__ ei,
                          const int* __restrict__ ew, int E) {
    int lane = threadIdx.x & 31;
    int warp = (blockIdx.x * blockDim.x + threadIdx.x) >> 5;
    int base = warp * 32;
    if (base >= E) return;

    // lane e-th edge meta (coalesced)
    int e = base + lane;
    u64 mpack = 0;
    float wgt = 0.f;
    if (e < E) {
        int d = ew[e];
        if (d >= 1 && d <= KH) {
            wgt = g_hopw[d - 1];
            int r = ei[e];        // row
            int c = ei[E + e];    // col
            mpack = ((u64)(unsigned)r << 32) | (unsigned)c;
        }
    }

    #pragma unroll 4
    for (int j = 0; j < 32; j++) {
        float w = __shfl_sync(0xffffffffu, wgt, j);   // uniform across warp
        if (w == 0.f) continue;
        u64 m = __shfl_sync(0xffffffffu, mpack, j);
        int c = (int)(unsigned)m;
        int r = (int)(unsigned)(m >> 32);
        float4 v = ((const float4*)x)[(size_t)c * 32 + lane];
        v.x *= w; v.y *= w; v.z *= w; v.w *= w;
        atomicAdd(((float4*)g_h) + (size_t)r * 32 + lane, v);   // RED.128
    }
}

// ---------------- GEMM + fused BN-stats epilogue ----------------
// PHASE 1: A = g_h + x (GIN self term), Y = g_y, stats -> g_st1
// PHASE 2: A = relu(a1*g_y + c1), Y = OutY, stats -> g_st2
// A stored as packed f32x2 row-pairs Apair[p][k] (u64, stride 130) so the
// mainloop reads 2 k-steps of a pair with ONE broadcast LDS.128.
// 256 threads: (tr=tid>>5, tc=tid&31) -> rows tr*8..+7, cols tc*4..+3.
#define APSTRIDE 130
template <int PHASE>
__global__ void __launch_bounds__(256) k_gemm(const float4* __restrict__ X,
                                              const float* __restrict__ W,
                                              float* __restrict__ OutY, int n) {
    const float* A = (PHASE == 1) ? g_h : g_y;
    float* Y       = (PHASE == 1) ? g_y : OutY;

    __shared__ __align__(16) float Ws[FDIM * 128];     // [k][c]  64 KB
    __shared__ __align__(16) u64 Apair[32 * APSTRIDE]; // [p][k]  33.3 KB
    __shared__ float sh_st[256];

    int tid = threadIdx.x;
    int tc = tid & 31, tr = tid >> 5;
    sh_st[tid] = 0.f;

    // stage W (coalesced, row-major [k][c])
    const float4* W4 = (const float4*)W;
    float4* Ws4 = (float4*)Ws;
    #pragma unroll 4
    for (int i = tid; i < FDIM * 32; i += 256) Ws4[i] = W4[i];

    // stage A as packed row-pairs: item i -> (pair p = i&31, c4 = i>>5)
    int row0 = blockIdx.x * 64;
    const float4* A4 = (const float4*)A;
    #pragma unroll
    for (int i = tid; i < 1024; i += 256) {
        int p = i & 31, c4 = i >> 5;
        int rlo = row0 + 2 * p;
        float4 vlo = make_float4(0.f, 0.f, 0.f, 0.f);
        float4 vhi = make_float4(0.f, 0.f, 0.f, 0.f);
        if (rlo < n)     vlo = A4[(size_t)rlo * 32 + c4];
        if (rlo + 1 < n) vhi = A4[(size_t)(rlo + 1) * 32 + c4];
        if (PHASE == 1) {
            if (rlo < n) {
                float4 xv = X[(size_t)rlo * 32 + c4];
                vlo.x += xv.x; vlo.y += xv.y; vlo.z += xv.z; vlo.w += xv.w;
            }
            if (rlo + 1 < n) {
                float4 xv = X[(size_t)(rlo + 1) * 32 + c4];
                vhi.x += xv.x; vhi.y += xv.y; vhi.z += xv.z; vhi.w += xv.w;
            }
        } else {
            float4 a = __ldg(&((const float4*)g_a1)[c4]);
            float4 b = __ldg(&((const float4*)g_c1)[c4]);
            vlo.x = fmaxf(fmaf(a.x, vlo.x, b.x), 0.f);
            vlo.y = fmaxf(fmaf(a.y, vlo.y, b.y), 0.f);
            vlo.z = fmaxf(fmaf(a.z, vlo.z, b.z), 0.f);
            vlo.w = fmaxf(fmaf(a.w, vlo.w, b.w), 0.f);
            vhi.x = fmaxf(fmaf(a.x, vhi.x, b.x), 0.f);
            vhi.y = fmaxf(fmaf(a.y, vhi.y, b.y), 0.f);
            vhi.z = fmaxf(fmaf(a.z, vhi.z, b.z), 0.f);
            vhi.w = fmaxf(fmaf(a.w, vhi.w, b.w), 0.f);
        }
        int k0 = c4 * 4;
        u64* dst = &Apair[p * APSTRIDE + k0];
        dst[0] = pk2(vlo.x, vhi.x);
        dst[1] = pk2(vlo.y, vhi.y);
        dst[2] = pk2(vlo.z, vhi.z);
        dst[3] = pk2(vlo.w, vhi.w);
    }
    __syncthreads();

    u64 acc[4][4];
    #pragma unroll
    for (int p = 0; p < 4; p++)
        #pragma unroll
        for (int c = 0; c < 4; c++) acc[p][c] = 0ULL;

    int p0 = tr * 4;
    #pragma unroll 8
    for (int k = 0; k < FDIM; k += 2) {
        // broadcast LDS.128: (k, k+1) of each of 4 row-pairs
        ulonglong2 q0 = *(const ulonglong2*)&Apair[(p0 + 0) * APSTRIDE + k];
        ulonglong2 q1 = *(const ulonglong2*)&Apair[(p0 + 1) * APSTRIDE + k];
        ulonglong2 q2 = *(const ulonglong2*)&Apair[(p0 + 2) * APSTRIDE + k];
        ulonglong2 q3 = *(const ulonglong2*)&Apair[(p0 + 3) * APSTRIDE + k];
        float4 wv0 = Ws4[k * 32 + tc];
        float4 wv1 = Ws4[(k + 1) * 32 + tc];

        u64 w0 = pk2(wv0.x, wv0.x);
        u64 w1 = pk2(wv0.y, wv0.y);
        u64 w2 = pk2(wv0.z, wv0.z);
        u64 w3 = pk2(wv0.w, wv0.w);
        FMA2(acc[0][0], q0.x, w0); FMA2(acc[0][1], q0.x, w1);
        FMA2(acc[0][2], q0.x, w2); FMA2(acc[0][3], q0.x, w3);
        FMA2(acc[1][0], q1.x, w0); FMA2(acc[1][1], q1.x, w1);
        FMA2(acc[1][2], q1.x, w2); FMA2(acc[1][3], q1.x, w3);
        FMA2(acc[2][0], q2.x, w0); FMA2(acc[2][1], q2.x, w1);
        FMA2(acc[2][2], q2.x, w2); FMA2(acc[2][3], q2.x, w3);
        FMA2(acc[3][0], q3.x, w0); FMA2(acc[3][1], q3.x, w1);
        FMA2(acc[3][2], q3.x, w2); FMA2(acc[3][3], q3.x, w3);

        w0 = pk2(wv1.x, wv1.x);
        w1 = pk2(wv1.y, wv1.y);
        w2 = pk2(wv1.z, wv1.z);
        w3 = pk2(wv1.w, wv1.w);
        FMA2(acc[0][0], q0.y, w0); FMA2(acc[0][1], q0.y, w1);
        FMA2(acc[0][2], q0.y, w2); FMA2(acc[0][3], q0.y, w3);
        FMA2(acc[1][0], q1.y, w0); FMA2(acc[1][1], q1.y, w1);
        FMA2(acc[1][2], q1.y, w2); FMA2(acc[1][3], q1.y, w3);
        FMA2(acc[2][0], q2.y, w0); FMA2(acc[2][1], q2.y, w1);
        FMA2(acc[2][2], q2.y, w2); FMA2(acc[2][3], q2.y, w3);
        FMA2(acc[3][0], q3.y, w0); FMA2(acc[3][1], q3.y, w1);
        FMA2(acc[3][2], q3.y, w2); FMA2(acc[3][3], q3.y, w3);
    }

    // epilogue: store Y + per-column stats
    float cs[4] = {0.f, 0.f, 0.f, 0.f};
    float cq[4] = {0.f, 0.f, 0.f, 0.f};
    int r0 = tr * 8;
    #pragma unroll
    for (int p = 0; p < 4; p++) {
        float2 c0 = upk2(acc[p][0]);
        float2 c1 = upk2(acc[p][1]);
        float2 c2 = upk2(acc[p][2]);
        float2 c3 = upk2(acc[p][3]);
        int r_lo = row0 + r0 + 2 * p;
        int r_hi = r_lo + 1;
        if (r_lo < n) {
            float4 o = make_float4(c0.x, c1.x, c2.x, c3.x);
            ((float4*)Y)[(size_t)r_lo * 32 + tc] = o;
            cs[0] += o.x; cs[1] += o.y; cs[2] += o.z; cs[3] += o.w;
            cq[0] += o.x * o.x; cq[1] += o.y * o.y;
            cq[2] += o.z * o.z; cq[3] += o.w * o.w;
        }
        if (r_hi < n) {
            float4 o = make_float4(c0.y, c1.y, c2.y, c3.y);
            ((float4*)Y)[(size_t)r_hi * 32 + tc] = o;
            cs[0] += o.x; cs[1] += o.y; cs[2] += o.z; cs[3] += o.w;
            cq[0] += o.x * o.x; cq[1] += o.y * o.y;
            cq[2] += o.z * o.z; cq[3] += o.w * o.w;
        }
    }
    #pragma unroll
    for (int c = 0; c < 4; c++) {
        atomicAdd(&sh_st[tc * 4 + c], cs[c]);
        atomicAdd(&sh_st[128 + tc * 4 + c], cq[c]);
    }
    __syncthreads();
    float* gst = (PHASE == 1) ? g_st1 : g_st2;
    atomicAdd(&gst[tid], sh_st[tid]);
}

// ---------------- BN finalize ----------------
template <int PHASE>
__global__ void k_bnfin(const float* __restrict__ gamma,
                        const float* __restrict__ beta, float invN) {
    int i = threadIdx.x;
    const float* st = (PHASE == 1) ? g_st1 : g_st2;
    float mean = st[i] * invN;
    float var = st[i + 128] * invN - mean * mean;
    float s = gamma[i] * rsqrtf(var + BN_EPS);
    if (PHASE == 1) { g_a1[i] = s; g_c1[i] = beta[i] - mean * s; }
    else            { g_a2[i] = s; g_c2[i] = beta[i] - mean * s; }
}

// ---------------- final BN2 + ReLU in place on d_out ----------------
__global__ void k_final(float4* __restrict__ y, int n4) {
    for (int i = blockIdx.x * blockDim.x + threadIdx.x; i < n4;
         i += gridDim.x * blockDim.x) {
        int c4 = i & 31;
        float4 a = __ldg(&((const float4*)g_a2)[c4]);
        float4 b = __ldg(&((const float4*)g_c2)[c4]);
        float4 v = y[i];
        v.x = fmaxf(fmaf(a.x, v.x, b.x), 0.f);
        v.y = fmaxf(fmaf(a.y, v.y, b.y), 0.f);
        v.z = fmaxf(fmaf(a.z, v.z, b.z), 0.f);
        v.w = fmaxf(fmaf(a.w, v.w, b.w), 0.f);
        y[i] = v;
    }
}

// ---------------- launcher ----------------
extern "C" void kernel_launch(void* const* d_in, const int* in_sizes, int n_in,
                              void* d_out, int out_size) {
    const float* x    = (const float*)d_in[0];   // [N,128]
    const int*   ei   = (const int*)  d_in[1];   // [2,E]
    const int*   ew   = (const int*)  d_in[2];   // [E]
    const float* hop  = (const float*)d_in[3];   // [5]
    const float* W1   = (const float*)d_in[4];   // [128,128]
    const float* g1   = (const float*)d_in[6];
    const float* be1  = (const float*)d_in[7];
    const float* W2   = (const float*)d_in[8];
    const float* g2   = (const float*)d_in[10];
    const float* be2  = (const float*)d_in[11];
    float* out = (float*)d_out;

    int n = in_sizes[0] / FDIM;   // 100000
    int E = in_sizes[2];          // 1600000
    int n4 = n * 32;
    float invN = 1.f / (float)n;

    k_prep<<<1, 256>>>(hop);
    k_zero_h<<<2048, 256>>>(n4);
    k_scatter<<<(E + 255) / 256, 256>>>(x, ei, ew, E);   // warp = 32 edges

    int gblocks = (n + 63) / 64;
    k_gemm<1><<<gblocks, 256>>>((const float4*)x, W1, nullptr, n);
    k_bnfin<1><<<1, 128>>>(g1, be1, invN);
    k_gemm<2><<<gblocks, 256>>>(nullptr, W2, out, n);
    k_bnfin<2><<<1, 128>>>(g2, be2, invN);
    k_final<<<2048, 256>>>((float4*)out, n4);
}

// round 8
// speedup vs baseline: 2.3577x; 1.0278x over previous
#include <cuda_runtime.h>

#define FDIM 128
#define KH 5
#define NMAX 100000
#define BN_EPS 1e-5f

typedef unsigned long long u64;

// ---------------- device scratch (static, no allocs) ----------------
__device__ float g_h[(size_t)NMAX * FDIM];   // agg  (51.2 MB)
__device__ float g_y[(size_t)NMAX * FDIM];   // y1   (51.2 MB)
__device__ float g_hopw[8];
__device__ float g_st1[256];                 // [0:128) colsum, [128:256) colsumsq
__device__ float g_st2[256];
__device__ float g_a1[FDIM], g_c1[FDIM];     // BN1 fused scale/shift
__device__ float g_a2[FDIM], g_c2[FDIM];     // BN2 fused scale/shift

// ---------------- f32x2 helpers ----------------
__device__ __forceinline__ u64 pk2(float lo, float hi) {
    u64 r;
    asm("mov.b64 %0, {%1, %2};" : "=l"(r) : "f"(lo), "f"(hi));
    return r;
}
__device__ __forceinline__ float2 upk2(u64 v) {
    float2 r;
    asm("mov.b64 {%0, %1}, %2;" : "=f"(r.x), "=f"(r.y) : "l"(v));
    return r;
}
#define FMA2(d, a, b) asm("fma.rn.f32x2 %0, %1, %2, %0;" : "+l"(d) : "l"(a), "l"(b))

// ---------------- softmax + zero stats ----------------
__global__ void k_prep(const float* __restrict__ hop_coef) {
    int t = threadIdx.x;
    if (t < 256) { g_st1[t] = 0.f; g_st2[t] = 0.f; }
    if (t == 0) {
        float v[KH];
        float m = -1e30f;
        for (int i = 0; i < KH; i++) { v[i] = hop_coef[i]; m = fmaxf(m, v[i]); }
        float s = 0.f;
        for (int i = 0; i < KH; i++) { v[i] = expf(v[i] - m); s += v[i]; }
        float inv = 1.f / s;
        for (int i = 0; i < KH; i++) g_hopw[i] = v[i] * inv;
    }
}

// ---------------- zero g_h ----------------
__global__ void k_zero_h(int n4) {
    float4 z = make_float4(0.f, 0.f, 0.f, 0.f);
    float4* h4 = (float4*)g_h;
    for (int i = blockIdx.x * blockDim.x + threadIdx.x; i < n4;
         i += gridDim.x * blockDim.x)
        h4[i] = z;
}

// ---------------- scatter-add: warp handles 32 edges, meta de-duplicated (R6 winner) ----------------
__global__ void k_scatter(const float* __restrict__ x,
                          const int* __restrict__ ei,
                          const int* __restrict__ ew, int E) {
    int lane = threadIdx.x & 31;
    int warp = (blockIdx.x * blockDim.x + threadIdx.x) >> 5;
    int base = warp * 32;
    if (base >= E) return;

    // lane e-th edge meta (coalesced)
    int e = base + lane;
    u64 mpack = 0;
    float wgt = 0.f;
    if (e < E) {
        int d = ew[e];
        if (d >= 1 && d <= KH) {
            wgt = g_hopw[d - 1];
            int r = ei[e];        // row
            int c = ei[E + e];    // col
            mpack = ((u64)(unsigned)r << 32) | (unsigned)c;
        }
    }

    #pragma unroll 4
    for (int j = 0; j < 32; j++) {
        float w = __shfl_sync(0xffffffffu, wgt, j);   // uniform across warp
        if (w == 0.f) continue;
        u64 m = __shfl_sync(0xffffffffu, mpack, j);
        int c = (int)(unsigned)m;
        int r = (int)(unsigned)(m >> 32);
        float4 v = ((const float4*)x)[(size_t)c * 32 + lane];
        v.x *= w; v.y *= w; v.z *= w; v.w *= w;
        atomicAdd(((float4*)g_h) + (size_t)r * 32 + lane, v);   // RED.128
    }
}

// ---------------- GEMM + fused BN-stats epilogue (R5 winner) ----------------
// PHASE 1: A = g_h + x (GIN self term fused at stage), Y = g_y, stats -> g_st1
// PHASE 2: A = relu(a1*g_y + c1), Y = OutY, stats -> g_st2
// A tile stored TRANSPOSED At[k][r] so row-pairs are broadcast LDS.64.
// 256 threads: (tr=tid>>5, tc=tid&31) -> rows tr*8..+7, cols tc*4..+3.
template <int PHASE>
__global__ void __launch_bounds__(256) k_gemm(const float4* __restrict__ X,
                                              const float* __restrict__ W,
                                              float* __restrict__ OutY, int n) {
    const float* A = (PHASE == 1) ? g_h : g_y;
    float* Y       = (PHASE == 1) ? g_y : OutY;

    __shared__ __align__(16) float Ws[FDIM * 128];   // [k][c]  64 KB
    __shared__ __align__(16) float At[FDIM * 64];    // [k][r]  32 KB (transposed)
    __shared__ float sh_st[256];

    int tid = threadIdx.x;
    int tc = tid & 31, tr = tid >> 5;
    sh_st[tid] = 0.f;

    // stage W (coalesced, row-major [k][c])
    const float4* W4 = (const float4*)W;
    float4* Ws4 = (float4*)Ws;
    #pragma unroll 4
    for (int i = tid; i < FDIM * 32; i += 256) Ws4[i] = W4[i];

    // stage A transposed: i -> (c4 = i>>6, r = i&63); within a warp lanes span r
    // => STS banks = r%32 conflict-free; LDG 512B-strided but sector-complete.
    int row0 = blockIdx.x * 64;
    const float4* A4 = (const float4*)A;
    #pragma unroll
    for (int i = tid; i < 2048; i += 256) {
        int c4 = i >> 6, r = i & 63;
        float4 v = make_float4(0.f, 0.f, 0.f, 0.f);
        if (row0 + r < n) {
            v = A4[(size_t)(row0 + r) * 32 + c4];
            if (PHASE == 1) {
                float4 xv = X[(size_t)(row0 + r) * 32 + c4];
                v.x += xv.x; v.y += xv.y; v.z += xv.z; v.w += xv.w;
            } else {
                float4 a = __ldg(&((const float4*)g_a1)[c4]);
                float4 b = __ldg(&((const float4*)g_c1)[c4]);
                v.x = fmaxf(fmaf(a.x, v.x, b.x), 0.f);
                v.y = fmaxf(fmaf(a.y, v.y, b.y), 0.f);
                v.z = fmaxf(fmaf(a.z, v.z, b.z), 0.f);
                v.w = fmaxf(fmaf(a.w, v.w, b.w), 0.f);
            }
        }
        int k0 = c4 * 4;
        At[(k0 + 0) * 64 + r] = v.x;
        At[(k0 + 1) * 64 + r] = v.y;
        At[(k0 + 2) * 64 + r] = v.z;
        At[(k0 + 3) * 64 + r] = v.w;
    }
    __syncthreads();

    u64 acc[4][4];
    #pragma unroll
    for (int p = 0; p < 4; p++)
        #pragma unroll
        for (int c = 0; c < 4; c++) acc[p][c] = 0ULL;

    int r0 = tr * 8;
    #pragma unroll 4
    for (int k = 0; k < FDIM; k++) {
        float4 wv = Ws4[k * 32 + tc];                    // LDS.128, conflict-free
        u64 w0 = pk2(wv.x, wv.x);
        u64 w1 = pk2(wv.y, wv.y);
        u64 w2 = pk2(wv.z, wv.z);
        u64 w3 = pk2(wv.w, wv.w);
        const u64* ak = (const u64*)&At[k * 64 + r0];    // broadcast LDS.64 pairs
        u64 a0 = ak[0];
        u64 a1 = ak[1];
        u64 a2 = ak[2];
        u64 a3 = ak[3];
        FMA2(acc[0][0], a0, w0); FMA2(acc[0][1], a0, w1);
        FMA2(acc[0][2], a0, w2); FMA2(acc[0][3], a0, w3);
        FMA2(acc[1][0], a1, w0); FMA2(acc[1][1], a1, w1);
        FMA2(acc[1][2], a1, w2); FMA2(acc[1][3], a1, w3);
        FMA2(acc[2][0], a2, w0); FMA2(acc[2][1], a2, w1);
        FMA2(acc[2][2], a2, w2); FMA2(acc[2][3], a2, w3);
        FMA2(acc[3][0], a3, w0); FMA2(acc[3][1], a3, w1);
        FMA2(acc[3][2], a3, w2); FMA2(acc[3][3], a3, w3);
    }

    // epilogue: store Y + per-column stats
    float cs[4] = {0.f, 0.f, 0.f, 0.f};
    float cq[4] = {0.f, 0.f, 0.f, 0.f};
    #pragma unroll
    for (int p = 0; p < 4; p++) {
        float2 c0 = upk2(acc[p][0]);
        float2 c1 = upk2(acc[p][1]);
        float2 c2 = upk2(acc[p][2]);
        float2 c3 = upk2(acc[p][3]);
        int r_lo = row0 + r0 + 2 * p;
        int r_hi = r_lo + 1;
        if (r_lo < n) {
            float4 o = make_float4(c0.x, c1.x, c2.x, c3.x);
            ((float4*)Y)[(size_t)r_lo * 32 + tc] = o;
            cs[0] += o.x; cs[1] += o.y; cs[2] += o.z; cs[3] += o.w;
            cq[0] += o.x * o.x; cq[1] += o.y * o.y;
            cq[2] += o.z * o.z; cq[3] += o.w * o.w;
        }
        if (r_hi < n) {
            float4 o = make_float4(c0.y, c1.y, c2.y, c3.y);
            ((float4*)Y)[(size_t)r_hi * 32 + tc] = o;
            cs[0] += o.x; cs[1] += o.y; cs[2] += o.z; cs[3] += o.w;
            cq[0] += o.x * o.x; cq[1] += o.y * o.y;
            cq[2] += o.z * o.z; cq[3] += o.w * o.w;
        }
    }
    #pragma unroll
    for (int c = 0; c < 4; c++) {
        atomicAdd(&sh_st[tc * 4 + c], cs[c]);
        atomicAdd(&sh_st[128 + tc * 4 + c], cq[c]);
    }
    __syncthreads();
    float* gst = (PHASE == 1) ? g_st1 : g_st2;
    atomicAdd(&gst[tid], sh_st[tid]);
}

// ---------------- BN finalize ----------------
template <int PHASE>
__global__ void k_bnfin(const float* __restrict__ gamma,
                        const float* __restrict__ beta, float invN) {
    int i = threadIdx.x;
    const float* st = (PHASE == 1) ? g_st1 : g_st2;
    float mean = st[i] * invN;
    float var = st[i + 128] * invN - mean * mean;
    float s = gamma[i] * rsqrtf(var + BN_EPS);
    if (PHASE == 1) { g_a1[i] = s; g_c1[i] = beta[i] - mean * s; }
    else            { g_a2[i] = s; g_c2[i] = beta[i] - mean * s; }
}

// ---------------- final BN2 + ReLU in place on d_out ----------------
__global__ void k_final(float4* __restrict__ y, int n4) {
    for (int i = blockIdx.x * blockDim.x + threadIdx.x; i < n4;
         i += gridDim.x * blockDim.x) {
        int c4 = i & 31;
        float4 a = __ldg(&((const float4*)g_a2)[c4]);
        float4 b = __ldg(&((const float4*)g_c2)[c4]);
        float4 v = y[i];
        v.x = fmaxf(fmaf(a.x, v.x, b.x), 0.f);
        v.y = fmaxf(fmaf(a.y, v.y, b.y), 0.f);
        v.z = fmaxf(fmaf(a.z, v.z, b.z), 0.f);
        v.w = fmaxf(fmaf(a.w, v.w, b.w), 0.f);
        y[i] = v;
    }
}

// ---------------- launcher ----------------
extern "C" void kernel_launch(void* const* d_in, const int* in_sizes, int n_in,
                              void* d_out, int out_size) {
    const float* x    = (const float*)d_in[0];   // [N,128]
    const int*   ei   = (const int*)  d_in[1];   // [2,E]
    const int*   ew   = (const int*)  d_in[2];   // [E]
    const float* hop  = (const float*)d_in[3];   // [5]
    const float* W1   = (const float*)d_in[4];   // [128,128]
    const float* g1   = (const float*)d_in[6];
    const float* be1  = (const float*)d_in[7];
    const float* W2   = (const float*)d_in[8];
    const float* g2   = (const float*)d_in[10];
    const float* be2  = (const float*)d_in[11];
    float* out = (float*)d_out;

    int n = in_sizes[0] / FDIM;   // 100000
    int E = in_sizes[2];          // 1600000
    int n4 = n * 32;
    float invN = 1.f / (float)n;

    k_prep<<<1, 256>>>(hop);
    k_zero_h<<<2048, 256>>>(n4);
    k_scatter<<<(E + 255) / 256, 256>>>(x, ei, ew, E);   // warp = 32 edges

    int gblocks = (n + 63) / 64;
    k_gemm<1><<<gblocks, 256>>>((const float4*)x, W1, nullptr, n);
    k_bnfin<1><<<1, 128>>>(g1, be1, invN);
    k_gemm<2><<<gblocks, 256>>>(nullptr, W2, out, n);
    k_bnfin<2><<<1, 128>>>(g2, be2, invN);
    k_final<<<2048, 256>>>((float4*)out, n4);
}